// round 11
// baseline (speedup 1.0000x reference)
#include <cuda_runtime.h>

#define W   32
#define TPB 256

// Bloch-sphere evolution of a single qubit under per-step RX(x_t) RY(th0_t) RZ(th1_t),
// starting at |0> = (0,0,1); <Z> is the z-component. Full angles (no half-angle
// factor) because conjugation doubles the rotation angle on the Bloch sphere.
__global__ void __launch_bounds__(TPB) qreupload_kernel(
    const float* __restrict__ x,
    const float* __restrict__ theta,   // [W,2]
    const float* __restrict__ w,       // [1,1]
    const float* __restrict__ bias,    // [1]
    float* __restrict__ out,
    int B)
{
    __shared__ float4 g[W];   // per-step fixed Givens coeffs {cb, sb, cc, sc}

    int tid = threadIdx.x;
    if (tid < W) {
        float t0 = theta[tid * 2 + 0];
        float t1 = theta[tid * 2 + 1];
        float sb = __sinf(t0), cb = __cosf(t0);
        float sc = __sinf(t1), cc = __cosf(t1);
        g[tid] = make_float4(cb, sb, cc, sc);
    }
    __syncthreads();

    int b = blockIdx.x * TPB + tid;
    if (b >= B) return;

    // Hoist readout scalars so the epilogue STG doesn't stall on fresh LDGs.
    float wv = __ldg(w);
    float bv = __ldg(bias);

    // Load this row's 32 floats with 8 front-batched LDG.128 (MLP=8).
    const float4* xr = reinterpret_cast<const float4*>(x + (size_t)b * W);
    float4 chunks[8];
    #pragma unroll
    for (int i = 0; i < 8; i++) chunks[i] = xr[i];

    float xv[W];
    #pragma unroll
    for (int i = 0; i < 8; i++) {
        xv[4 * i + 0] = chunks[i].x;
        xv[4 * i + 1] = chunks[i].y;
        xv[4 * i + 2] = chunks[i].z;
        xv[4 * i + 3] = chunks[i].w;
    }

    float X = 0.0f, Y = 0.0f, Z = 1.0f;

    #pragma unroll
    for (int t = 0; t < W; t++) {
        float sx, cx;
        __sincosf(xv[t], &sx, &cx);          // FMUL + 2x MUFU
        float4 gv = g[t];                    // broadcast LDS.128

        // RX(x_t): rotate (Y,Z)
        float y1 = cx * Y - sx * Z;
        float z1 = sx * Y + cx * Z;
        // RY(th0): rotate (X, z1)
        float x1 = gv.x * X + gv.y * z1;
        Z        = gv.x * z1 - gv.y * X;
        // RZ(th1): rotate (x1, y1)
        X = gv.z * x1 - gv.w * y1;
        Y = gv.w * x1 + gv.z * y1;
    }

    out[b] = Z * wv + bv;
}

extern "C" void kernel_launch(void* const* d_in, const int* in_sizes, int n_in,
                              void* d_out, int out_size) {
    const float* x     = (const float*)d_in[0];
    const float* theta = (const float*)d_in[1];
    const float* w     = (const float*)d_in[2];
    const float* bias  = (const float*)d_in[3];
    float* out = (float*)d_out;

    int B = in_sizes[0] / W;     // 1048576
    int grid = (B + TPB - 1) / TPB;
    qreupload_kernel<<<grid, TPB>>>(x, theta, w, bias, out, B);
}

// round 14
// speedup vs baseline: 1.2091x; 1.2091x over previous
#include <cuda_runtime.h>

#define W   32
#define TPB 256
#define S   257   // padded row stride (floats): conflict-free for both scatter and read

__global__ void __launch_bounds__(TPB) qreupload_kernel(
    const float* __restrict__ x,
    const float* __restrict__ theta,   // [W,2]
    const float* __restrict__ w,       // [1,1]
    const float* __restrict__ bias,    // [1]
    float* __restrict__ out,
    int B)
{
    __shared__ float  xs[W * S];   // transposed tile: xs[col*S + row], 32*257*4 = 32896 B
    __shared__ float4 g[W];        // per-step Givens coeffs {cb, sb, cc, sc}

    int tid = threadIdx.x;
    if (tid < W) {
        float t0 = theta[tid * 2 + 0];
        float t1 = theta[tid * 2 + 1];
        float sb = __sinf(t0), cb = __cosf(t0);
        float sc = __sinf(t1), cc = __cosf(t1);
        g[tid] = make_float4(cb, sb, cc, sc);
    }

    // ---- Coalesced load + transpose into shared -------------------------
    // Warp layout: c = lane%8 picks the float4 column, tid/8 picks the row.
    // Per LDG.128 a warp reads 32 consecutive float4 (512 B = 4 lines).
    // Scatter banks: (4c+j)*257 + row  ≡  (4c + j + tid/8) mod 32 — all 32
    // lanes distinct for fixed j → conflict-free STS.
    int R0 = blockIdx.x * TPB;
    int c  = tid & 7;
    int r  = tid >> 3;
    const float4* __restrict__ x4 = reinterpret_cast<const float4*>(x);

    #pragma unroll
    for (int half = 0; half < 2; half++) {
        float4 v[4];
        #pragma unroll
        for (int k = 0; k < 4; k++) {               // batch 4 LDGs (MLP=4)
            int row = r + (half * 4 + k) * 32;
            int gr  = R0 + row;
            v[k] = (gr < B) ? x4[(size_t)gr * 8 + c]
                            : make_float4(0.f, 0.f, 0.f, 0.f);
        }
        #pragma unroll
        for (int k = 0; k < 4; k++) {
            int row = r + (half * 4 + k) * 32;
            xs[(4 * c + 0) * S + row] = v[k].x;
            xs[(4 * c + 1) * S + row] = v[k].y;
            xs[(4 * c + 2) * S + row] = v[k].z;
            xs[(4 * c + 3) * S + row] = v[k].w;
        }
    }

    float wv = __ldg(w);
    float bv = __ldg(bias);
    __syncthreads();

    // ---- Bloch-vector evolution: RX(x_t) RY(th0) RZ(th1), start (0,0,1) --
    float X = 0.0f, Y = 0.0f, Z = 1.0f;

    #pragma unroll
    for (int t = 0; t < W; t++) {
        float xt = xs[t * S + tid];          // conflict-free LDS.32
        float sx, cx;
        __sincosf(xt, &sx, &cx);             // 2x MUFU
        float4 gv = g[t];                    // broadcast LDS.128

        // RX(x_t): rotate (Y,Z)
        float y1 = cx * Y - sx * Z;
        float z1 = sx * Y + cx * Z;
        // RY(th0): rotate (X, z1)
        float x1 = gv.x * X + gv.y * z1;
        Z        = gv.x * z1 - gv.y * X;
        // RZ(th1): rotate (x1, y1)
        X = gv.z * x1 - gv.w * y1;
        Y = gv.w * x1 + gv.z * y1;
    }

    int b = R0 + tid;
    if (b < B) out[b] = Z * wv + bv;
}

extern "C" void kernel_launch(void* const* d_in, const int* in_sizes, int n_in,
                              void* d_out, int out_size) {
    const float* x     = (const float*)d_in[0];
    const float* theta = (const float*)d_in[1];
    const float* w     = (const float*)d_in[2];
    const float* bias  = (const float*)d_in[3];
    float* out = (float*)d_out;

    int B = in_sizes[0] / W;     // 1048576
    int grid = (B + TPB - 1) / TPB;
    qreupload_kernel<<<grid, TPB>>>(x, theta, w, bias, out, B);
}